// round 3
// baseline (speedup 1.0000x reference)
#include <cuda_runtime.h>
#include <math.h>

// Problem constants
#define BQ   128      // batch
#define TQ   256      // timesteps
#define INQ  128      // input features
#define HQ   1024     // hidden
#define G4   4096     // 4*H gate width
#define NCTA 128      // persistent CTAs (<= 148 SMs -> all co-resident)
#define NTHR 256

// Persistent state (device globals: allocation-free scratch)
__device__ float g_h0[BQ * HQ];
__device__ float g_c0[BQ * HQ];
__device__ float g_h1[BQ * HQ];
__device__ float g_c1[BQ * HQ];
// K-split partial gate sums: [4 splits][B][4H] = 8 MB
__device__ float g_part[4ull * BQ * G4];

// Software grid barrier state
__device__ unsigned g_bar_count = 0;
__device__ unsigned g_bar_gen   = 0;

// ---------------------------------------------------------------------------
// Grid-wide barrier. Valid because all NCTA CTAs are co-resident (grid <= SMs).
// Release/acquire via __threadfence around the generation flip.
// ---------------------------------------------------------------------------
__device__ __forceinline__ void grid_bar() {
    __syncthreads();
    if (threadIdx.x == 0) {
        __threadfence();                       // publish this CTA's writes
        unsigned my = *(volatile unsigned*)&g_bar_gen;
        if (atomicAdd(&g_bar_count, 1u) == NCTA - 1u) {
            *(volatile unsigned*)&g_bar_count = 0;
            __threadfence();
            atomicExch(&g_bar_gen, my + 1u);   // release
        } else {
            while (*(volatile unsigned*)&g_bar_gen == my) { }
        }
        __threadfence();                       // acquire
    }
    __syncthreads();
}

// ---------------------------------------------------------------------------
// One K-chunk of the per-step gate GEMM (persistent-phase version).
//   g_part[s] = A0[:, chunk] @ W0^T + A1[:, chunk] @ W1^T
// Virtual K axis = [0, K0) from (A0,W0) then onwards from (A1,W1).
// CTA covers a 128(batch) x 128(gate-col) tile: 32 hidden cols x 4 gates.
// 8x8 per-thread microtile, BK=16, register-staged pipeline over L2 loads.
// ---------------------------------------------------------------------------
__device__ __forceinline__ void gemm_phase(
    const float* __restrict__ A0, int lda0, int K0,
    const float* __restrict__ W0, int ldw0,
    const float* __restrict__ A1, int lda1,
    const float* __restrict__ W1, int ldw1,
    int kc, int n0, int s,
    float (*As)[132], float (*Bs)[132])
{
    const int tid  = threadIdx.x;
    const int tym  = tid >> 4;    // 0..15 row group
    const int txn  = tid & 15;    // 0..15 col group
    const int kk_l = tid & 15;    // loader: k within BK block
    const int rr   = tid >> 4;    // loader: row base

    const int klo = s * kc;
    const int khi = klo + kc;

    float acc[8][8];
    #pragma unroll
    for (int i = 0; i < 8; ++i)
        #pragma unroll
        for (int j = 0; j < 8; ++j) acc[i][j] = 0.f;

    float ra[8], rb[8];

    // prologue load (kb = klo)
    {
        const float* A; const float* W; int lda, ldw, ks;
        if (klo < K0) { A = A0; lda = lda0; W = W0; ldw = ldw0; ks = klo; }
        else          { A = A1; lda = lda1; W = W1; ldw = ldw1; ks = klo - K0; }
        #pragma unroll
        for (int r = 0; r < 8; ++r) {
            int m = rr + r * 16;
            ra[r] = A[(size_t)m * lda + ks + kk_l];
            int g = ((m >> 5) << 10) + n0 + (m & 31);
            rb[r] = W[(size_t)g * ldw + ks + kk_l];
        }
    }

    for (int kb = klo; kb < khi; kb += 16) {
        // stage registers -> smem
        #pragma unroll
        for (int r = 0; r < 8; ++r) {
            int m = rr + r * 16;
            As[kk_l][m] = ra[r];
            Bs[kk_l][m] = rb[r];
        }
        __syncthreads();

        // issue next slab's loads (overlaps with compute below)
        int kn = kb + 16;
        if (kn < khi) {
            const float* A; const float* W; int lda, ldw, ks;
            if (kn < K0) { A = A0; lda = lda0; W = W0; ldw = ldw0; ks = kn; }
            else         { A = A1; lda = lda1; W = W1; ldw = ldw1; ks = kn - K0; }
            #pragma unroll
            for (int r = 0; r < 8; ++r) {
                int m = rr + r * 16;
                ra[r] = A[(size_t)m * lda + ks + kk_l];
                int g = ((m >> 5) << 10) + n0 + (m & 31);
                rb[r] = W[(size_t)g * ldw + ks + kk_l];
            }
        }

        #pragma unroll
        for (int kk = 0; kk < 16; ++kk) {
            float a[8], b[8];
            float4 a0 = *(const float4*)&As[kk][tym * 8];
            float4 a1 = *(const float4*)&As[kk][tym * 8 + 4];
            float4 b0 = *(const float4*)&Bs[kk][txn * 8];
            float4 b1 = *(const float4*)&Bs[kk][txn * 8 + 4];
            a[0]=a0.x; a[1]=a0.y; a[2]=a0.z; a[3]=a0.w;
            a[4]=a1.x; a[5]=a1.y; a[6]=a1.z; a[7]=a1.w;
            b[0]=b0.x; b[1]=b0.y; b[2]=b0.z; b[3]=b0.w;
            b[4]=b1.x; b[5]=b1.y; b[6]=b1.z; b[7]=b1.w;
            #pragma unroll
            for (int i = 0; i < 8; ++i)
                #pragma unroll
                for (int j = 0; j < 8; ++j)
                    acc[i][j] = fmaf(a[i], b[j], acc[i][j]);
        }
        __syncthreads();
    }

    // store partial tile
    const int gate  = txn >> 2;
    const int nloc  = (txn * 8) & 31;
    const int gbase = (gate << 10) + n0 + nloc;
    #pragma unroll
    for (int i = 0; i < 8; ++i) {
        int m = tym * 8 + i;
        float* p = &g_part[((size_t)(s * BQ + m)) * G4 + gbase];
        *(float4*)p       = make_float4(acc[i][0], acc[i][1], acc[i][2], acc[i][3]);
        *(float4*)(p + 4) = make_float4(acc[i][4], acc[i][5], acc[i][6], acc[i][7]);
    }
}

// ---------------------------------------------------------------------------
// LSTM pointwise cell update phase: sum 4 K-split partials + biases, update c,h
// Gate order: i, f, g, o
// ---------------------------------------------------------------------------
__device__ __forceinline__ void cell_phase(
    float* __restrict__ c, float* __restrict__ h,
    const float* __restrict__ b_ih, const float* __restrict__ b_hh)
{
    const int gtid = blockIdx.x * NTHR + threadIdx.x;    // 0..32767
    #pragma unroll
    for (int it = 0; it < (BQ * HQ) / (NCTA * NTHR); ++it) {
        int idx = gtid + it * NCTA * NTHR;
        int b = idx >> 10;
        int n = idx & 1023;

        float gi = 0.f, gf = 0.f, gg = 0.f, go = 0.f;
        #pragma unroll
        for (int s = 0; s < 4; ++s) {
            const float* p = &g_part[((size_t)(s * BQ + b)) * G4];
            gi += p[n];
            gf += p[1024 + n];
            gg += p[2048 + n];
            go += p[3072 + n];
        }
        gi += b_ih[n]        + b_hh[n];
        gf += b_ih[1024 + n] + b_hh[1024 + n];
        gg += b_ih[2048 + n] + b_hh[2048 + n];
        go += b_ih[3072 + n] + b_hh[3072 + n];

        float si = 1.f / (1.f + expf(-gi));
        float sf = 1.f / (1.f + expf(-gf));
        float so = 1.f / (1.f + expf(-go));
        float cn = sf * c[idx] + si * tanhf(gg);
        c[idx] = cn;
        h[idx] = so * tanhf(cn);
    }
}

// ---------------------------------------------------------------------------
// The entire network in one persistent kernel.
// ---------------------------------------------------------------------------
__global__ __launch_bounds__(NTHR) void lstm_persistent_kernel(
    const float* __restrict__ x,
    const float* __restrict__ W_ih0, const float* __restrict__ W_hh0,
    const float* __restrict__ b_ih0, const float* __restrict__ b_hh0,
    const float* __restrict__ W_ih1, const float* __restrict__ W_hh1,
    const float* __restrict__ b_ih1, const float* __restrict__ b_hh1,
    const float* __restrict__ Wd,    const float* __restrict__ bd,
    float* __restrict__ out)
{
    __shared__ float As[16][132];
    __shared__ float Bs[16][132];
    __shared__ float red[NTHR];

    const int cta = blockIdx.x;
    const int tid = threadIdx.x;
    const int n0  = (cta & 31) * 32;   // hidden-column tile base
    const int s   = cta >> 5;          // K-split index

    // init recurrent state
    for (int i = cta * NTHR + tid; i < BQ * HQ; i += NCTA * NTHR) {
        g_h0[i] = 0.f; g_c0[i] = 0.f; g_h1[i] = 0.f; g_c1[i] = 0.f;
    }
    grid_bar();

    for (int t = 0; t < TQ; ++t) {
        // Layer 0: virtual K = 128 (x_t, W_ih0) ++ 1024 (h0, W_hh0); kc = 288
        gemm_phase(x + (size_t)t * INQ, TQ * INQ, INQ, W_ih0, INQ,
                   g_h0, HQ, W_hh0, HQ, 288, n0, s, As, Bs);
        grid_bar();
        cell_phase(g_c0, g_h0, b_ih0, b_hh0);
        grid_bar();

        // Layer 1: virtual K = 1024 (h0, W_ih1) ++ 1024 (h1, W_hh1); kc = 512
        gemm_phase(g_h0, HQ, HQ, W_ih1, HQ,
                   g_h1, HQ, W_hh1, HQ, 512, n0, s, As, Bs);
        grid_bar();
        cell_phase(g_c1, g_h1, b_ih1, b_hh1);
        grid_bar();
    }

    // Dense head + tanh: CTA b computes out[b][0..1]
    const int b = cta;
    float s0 = 0.f, s1 = 0.f;
    for (int n = tid; n < HQ; n += NTHR) {
        float hv = g_h1[b * HQ + n];
        s0 += hv * Wd[n];
        s1 += hv * Wd[HQ + n];
    }
    red[tid] = s0;
    __syncthreads();
    for (int off = NTHR / 2; off > 0; off >>= 1) {
        if (tid < off) red[tid] += red[tid + off];
        __syncthreads();
    }
    if (tid == 0) out[b * 2 + 0] = tanhf(red[0] + bd[0]);
    __syncthreads();
    red[tid] = s1;
    __syncthreads();
    for (int off = NTHR / 2; off > 0; off >>= 1) {
        if (tid < off) red[tid] += red[tid + off];
        __syncthreads();
    }
    if (tid == 0) out[b * 2 + 1] = tanhf(red[0] + bd[1]);
}

// ---------------------------------------------------------------------------
// Launch: ONE kernel node -> tiny graph, no upload-allocation leak.
// ---------------------------------------------------------------------------
extern "C" void kernel_launch(void* const* d_in, const int* in_sizes, int n_in,
                              void* d_out, int out_size)
{
    const float* x     = (const float*)d_in[0];
    const float* W_ih0 = (const float*)d_in[1];
    const float* W_hh0 = (const float*)d_in[2];
    const float* b_ih0 = (const float*)d_in[3];
    const float* b_hh0 = (const float*)d_in[4];
    const float* W_ih1 = (const float*)d_in[5];
    const float* W_hh1 = (const float*)d_in[6];
    const float* b_ih1 = (const float*)d_in[7];
    const float* b_hh1 = (const float*)d_in[8];
    const float* Wd    = (const float*)d_in[9];
    const float* bd    = (const float*)d_in[10];
    float* out = (float*)d_out;

    lstm_persistent_kernel<<<NCTA, NTHR>>>(
        x, W_ih0, W_hh0, b_ih0, b_hh0,
        W_ih1, W_hh1, b_ih1, b_hh1, Wd, bd, out);
}

// round 5
// speedup vs baseline: 1.9803x; 1.9803x over previous
#include <cuda_runtime.h>
#include <cuda_bf16.h>
#include <math.h>

// Problem constants
#define BQ   128
#define TQ   256
#define INQ  128
#define HQ   1024
#define NCTA 128      // 32 col-tiles x 4 K-splits; all co-resident (<=148 SMs)
#define NTHR 256

#define KV0  1152     // layer0 virtual K = 128 (x) + 1024 (h0)
#define KV1  2048     // layer1 virtual K = 1024 (h0) + 1024 (h1)

// SMEM stage: 4 tiles (A_hi, A_lo, W_hi, W_lo), each 128 rows x 32 bf16,
// padded row stride 40 bf16 = 80B (conflict-free ldmatrix).
#define TILEB  10240u             // 128*80
#define STAGEB 40960u             // 4*TILEB
#define NBUF   3

// ---------------------------------------------------------------------------
// Device globals (allocation-free scratch)
// ---------------------------------------------------------------------------
// Split-bf16 weights, tile-permuted: row (tile*128 + r) maps to gate column
// (r>>5)*1024 + tile*32 + (r&31); columns = virtual K.
__device__ __nv_bfloat16 g_W0h[32 * 128 * KV0];
__device__ __nv_bfloat16 g_W0l[32 * 128 * KV0];
__device__ __nv_bfloat16 g_W1h[32 * 128 * KV1];
__device__ __nv_bfloat16 g_W1l[32 * 128 * KV1];
__device__ __nv_bfloat16 g_xh[BQ * TQ * INQ];    // [b][t][k]
__device__ __nv_bfloat16 g_xl[BQ * TQ * INQ];
__device__ __nv_bfloat16 g_h0h[BQ * HQ];          // [b][n]
__device__ __nv_bfloat16 g_h0l[BQ * HQ];
__device__ __nv_bfloat16 g_h1h[BQ * HQ];
__device__ __nv_bfloat16 g_h1l[BQ * HQ];
__device__ float g_h1f[BQ * HQ];                  // fp32 h1 for the head
__device__ float g_c0[BQ * HQ];                   // [b][n]
__device__ float g_c1[BQ * HQ];
// Partial gate sums: [s][tile][b 0..127][c 0..127]  (8 MB)
__device__ float g_part[4u * 32u * 128u * 128u];

__device__ unsigned g_bar_count = 0;
__device__ unsigned g_bar_gen   = 0;

// ---------------------------------------------------------------------------
// PTX helpers (all plain sm_80+ — safe at compute_103)
// ---------------------------------------------------------------------------
__device__ __forceinline__ unsigned smem_u32(const void* p) {
    unsigned a;
    asm("{ .reg .u64 t; cvta.to.shared.u64 t, %1; cvt.u32.u64 %0, t; }"
        : "=r"(a) : "l"(p));
    return a;
}
__device__ __forceinline__ void cp16(unsigned dst, const void* src) {
    asm volatile("cp.async.cg.shared.global [%0], [%1], 16;"
                 :: "r"(dst), "l"(src) : "memory");
}
__device__ __forceinline__ void cp_commit() {
    asm volatile("cp.async.commit_group;" ::: "memory");
}
template <int N>
__device__ __forceinline__ void cp_wait() {
    asm volatile("cp.async.wait_group %0;" :: "n"(N) : "memory");
}
__device__ __forceinline__ void ldsm4(unsigned& r0, unsigned& r1,
                                      unsigned& r2, unsigned& r3, unsigned a) {
    asm volatile("ldmatrix.sync.aligned.m8n8.x4.shared.b16 {%0,%1,%2,%3}, [%4];"
                 : "=r"(r0), "=r"(r1), "=r"(r2), "=r"(r3) : "r"(a));
}
__device__ __forceinline__ void ldsm2(unsigned& r0, unsigned& r1, unsigned a) {
    asm volatile("ldmatrix.sync.aligned.m8n8.x2.shared.b16 {%0,%1}, [%2];"
                 : "=r"(r0), "=r"(r1) : "r"(a));
}
__device__ __forceinline__ void mma16816(float* d, const unsigned* a, const unsigned* b) {
    asm volatile(
        "mma.sync.aligned.m16n8k16.row.col.f32.bf16.bf16.f32 "
        "{%0,%1,%2,%3}, {%4,%5,%6,%7}, {%8,%9}, {%0,%1,%2,%3};"
        : "+f"(d[0]), "+f"(d[1]), "+f"(d[2]), "+f"(d[3])
        : "r"(a[0]), "r"(a[1]), "r"(a[2]), "r"(a[3]), "r"(b[0]), "r"(b[1]));
}

// ---------------------------------------------------------------------------
// Grid barrier (all NCTA CTAs co-resident)
// ---------------------------------------------------------------------------
__device__ __forceinline__ void grid_bar() {
    __syncthreads();
    if (threadIdx.x == 0) {
        __threadfence();
        unsigned my = *(volatile unsigned*)&g_bar_gen;
        if (atomicAdd(&g_bar_count, 1u) == NCTA - 1u) {
            *(volatile unsigned*)&g_bar_count = 0;
            __threadfence();
            atomicExch(&g_bar_gen, my + 1u);
        } else {
            while (*(volatile unsigned*)&g_bar_gen == my) { }
        }
        __threadfence();
    }
    __syncthreads();
}

// ---------------------------------------------------------------------------
// Init kernels (run every replay; deterministic)
// ---------------------------------------------------------------------------
__device__ __forceinline__ void split2(float f, __nv_bfloat16& h, __nv_bfloat16& l) {
    h = __float2bfloat16(f);
    l = __float2bfloat16(f - __bfloat162float(h));
}

__global__ void init_state_kernel() {
    int i = blockIdx.x * blockDim.x + threadIdx.x;
    if (i < BQ * HQ) {
        g_h0h[i] = __float2bfloat16(0.f); g_h0l[i] = __float2bfloat16(0.f);
        g_h1h[i] = __float2bfloat16(0.f); g_h1l[i] = __float2bfloat16(0.f);
        g_c0[i] = 0.f; g_c1[i] = 0.f;
    }
}
__global__ void init_x_kernel(const float* __restrict__ x) {
    int i = blockIdx.x * blockDim.x + threadIdx.x;
    if (i < BQ * TQ * INQ) split2(x[i], g_xh[i], g_xl[i]);
}
__global__ void init_w_kernel(
    const float* __restrict__ W_ih0, const float* __restrict__ W_hh0,
    const float* __restrict__ W_ih1, const float* __restrict__ W_hh1)
{
    const unsigned N0 = 32u * 128u * KV0;
    const unsigned N1 = 32u * 128u * KV1;
    for (unsigned i = blockIdx.x * blockDim.x + threadIdx.x; i < N0 + N1;
         i += gridDim.x * blockDim.x) {
        if (i < N0) {
            unsigned k = i % KV0, r = (i / KV0) % 128u, tile = i / (KV0 * 128u);
            unsigned gcol = ((r >> 5) << 10) + tile * 32u + (r & 31u);
            float v = (k < 128u) ? W_ih0[(size_t)gcol * 128u + k]
                                 : W_hh0[(size_t)gcol * 1024u + (k - 128u)];
            split2(v, g_W0h[i], g_W0l[i]);
        } else {
            unsigned j = i - N0;
            unsigned k = j % KV1, r = (j / KV1) % 128u, tile = j / (KV1 * 128u);
            unsigned gcol = ((r >> 5) << 10) + tile * 32u + (r & 31u);
            float v = (k < 1024u) ? W_ih1[(size_t)gcol * 1024u + k]
                                  : W_hh1[(size_t)gcol * 1024u + (k - 1024u)];
            split2(v, g_W1h[j], g_W1l[j]);
        }
    }
}

// ---------------------------------------------------------------------------
// GEMM phase: units of 32 virtual-K, 3-term split bf16 HMMA, cp.async pipeline.
// CTA computes 128(batch) x 128(gate-col tile) partial, writes g_part[s][tile].
// Warp grid 2(M) x 4(N): warp tile 64 x 32.
// ---------------------------------------------------------------------------
__device__ void gemm_phase(
    const __nv_bfloat16* __restrict__ ah0, const __nv_bfloat16* __restrict__ al0, int lda0,
    const __nv_bfloat16* __restrict__ ah1, const __nv_bfloat16* __restrict__ al1, int lda1,
    int usplit,
    const __nv_bfloat16* __restrict__ wh, const __nv_bfloat16* __restrict__ wl, int ldw,
    int ulo, int uhi, unsigned sb, int tile, int s)
{
    const int tid  = threadIdx.x;
    const int lane = tid & 31;
    const int wid  = tid >> 5;
    const int wm   = wid >> 2;   // 0..1
    const int wn   = wid & 3;    // 0..3

    float acc[4][4][4];
    #pragma unroll
    for (int m = 0; m < 4; ++m)
        #pragma unroll
        for (int n = 0; n < 4; ++n)
            #pragma unroll
            for (int r = 0; r < 4; ++r) acc[m][n][r] = 0.f;

    const int nU = uhi - ulo;
    const __nv_bfloat16* whtile = wh + (size_t)tile * 128 * ldw;
    const __nv_bfloat16* wltile = wl + (size_t)tile * 128 * ldw;

    auto issue = [&](int idx) {
        int u = ulo + idx;
        const __nv_bfloat16 *ah, *al; int lda;
        if (u < usplit) { ah = ah0 + u * 32;             al = al0 + u * 32;             lda = lda0; }
        else            { ah = ah1 + (u - usplit) * 32;  al = al1 + (u - usplit) * 32;  lda = lda1; }
        const __nv_bfloat16* whp = whtile + u * 32;
        const __nv_bfloat16* wlp = wltile + u * 32;
        unsigned sbuf = sb + (unsigned)(idx % NBUF) * STAGEB;
        #pragma unroll
        for (int j = 0; j < 2; ++j) {
            int c = tid + j * 256;        // 0..511
            int row = c >> 2, kb = c & 3;
            unsigned dst = sbuf + (unsigned)(row * 80 + kb * 16);
            cp16(dst,              ah  + (size_t)row * lda + kb * 8);
            cp16(dst + TILEB,      al  + (size_t)row * lda + kb * 8);
            cp16(dst + 2 * TILEB,  whp + (size_t)row * ldw + kb * 8);
            cp16(dst + 3 * TILEB,  wlp + (size_t)row * ldw + kb * 8);
        }
        cp_commit();
    };

    issue(0);
    if (nU > 1) issue(1);

    for (int i = 0; i < nU; ++i) {
        if (i < nU - 1) cp_wait<1>(); else cp_wait<0>();
        __syncthreads();
        if (i + 2 < nU) issue(i + 2);

        unsigned sbuf = sb + (unsigned)(i % NBUF) * STAGEB;
        #pragma unroll
        for (int j = 0; j < 2; ++j) {
            // A fragments: rows wm*64 + m*16 .. ; ldmatrix x4 (hi and lo tiles)
            unsigned a_base = sbuf + (unsigned)((wm * 64 + (lane & 15)) * 80
                                                + j * 32 + (lane >> 4) * 16);
            unsigned AH[4][4], AL[4][4];
            #pragma unroll
            for (int m = 0; m < 4; ++m) {
                ldsm4(AH[m][0], AH[m][1], AH[m][2], AH[m][3], a_base + m * 1280u);
                ldsm4(AL[m][0], AL[m][1], AL[m][2], AL[m][3], a_base + m * 1280u + TILEB);
            }
            // W fragments: rows (gate cols) wn*32 + n*8 .. ; ldmatrix x2
            unsigned w_base = sbuf + 2 * TILEB
                            + (unsigned)((wn * 32 + (lane & 7)) * 80
                                         + j * 32 + ((lane >> 3) & 1) * 16);
            unsigned WH[4][2], WL[4][2];
            #pragma unroll
            for (int n = 0; n < 4; ++n) {
                ldsm2(WH[n][0], WH[n][1], w_base + n * 640u);
                ldsm2(WL[n][0], WL[n][1], w_base + n * 640u + TILEB);
            }
            #pragma unroll
            for (int m = 0; m < 4; ++m)
                #pragma unroll
                for (int n = 0; n < 4; ++n) {
                    mma16816(acc[m][n], AH[m], WH[n]);
                    mma16816(acc[m][n], AL[m], WH[n]);
                    mma16816(acc[m][n], AH[m], WL[n]);
                }
        }
    }

    // Epilogue: D fragment (m = batch, n = gate col) -> g_part[s][tile][b][c]
    float* pb = g_part + ((size_t)(s * 32 + tile) << 14);
    #pragma unroll
    for (int m = 0; m < 4; ++m)
        #pragma unroll
        for (int n = 0; n < 4; ++n) {
            int b = wm * 64 + m * 16 + (lane >> 2);
            int c = wn * 32 + n * 8 + (lane & 3) * 2;
            *(float2*)(pb + (size_t)b * 128 + c) =
                make_float2(acc[m][n][0], acc[m][n][1]);
            *(float2*)(pb + (size_t)(b + 8) * 128 + c) =
                make_float2(acc[m][n][2], acc[m][n][3]);
        }
}

// ---------------------------------------------------------------------------
// Cell phase: sum 4 K-split partials + biases; update c; emit split h.
// Gate order: i, f, g, o.
// ---------------------------------------------------------------------------
__device__ __forceinline__ void cell_phase(
    float* __restrict__ cst,
    __nv_bfloat16* __restrict__ hh, __nv_bfloat16* __restrict__ hl,
    float* __restrict__ hf,
    const float* __restrict__ b_ih, const float* __restrict__ b_hh)
{
    const int gtid = blockIdx.x * NTHR + threadIdx.x;
    #pragma unroll
    for (int it = 0; it < (BQ * HQ) / (NCTA * NTHR); ++it) {
        int gid  = gtid + it * NCTA * NTHR;   // = b*1024 + n
        int n    = gid & 1023;
        int b    = gid >> 10;
        int tile = n >> 5, nl = n & 31;

        float g4[4];
        #pragma unroll
        for (int g = 0; g < 4; ++g) {
            float sum = b_ih[g * 1024 + n] + b_hh[g * 1024 + n];
            #pragma unroll
            for (int s2 = 0; s2 < 4; ++s2)
                sum += g_part[((size_t)(s2 * 32 + tile) << 14)
                              + (size_t)b * 128 + g * 32 + nl];
            g4[g] = sum;
        }
        float si = 1.f / (1.f + expf(-g4[0]));
        float sf = 1.f / (1.f + expf(-g4[1]));
        float so = 1.f / (1.f + expf(-g4[3]));
        float cn = sf * cst[gid] + si * tanhf(g4[2]);
        cst[gid] = cn;
        float hv = so * tanhf(cn);
        __nv_bfloat16 hb = __float2bfloat16(hv);
        hh[gid] = hb;
        hl[gid] = __float2bfloat16(hv - __bfloat162float(hb));
        if (hf) hf[gid] = hv;
    }
}

// ---------------------------------------------------------------------------
// Main persistent kernel
// ---------------------------------------------------------------------------
__global__ __launch_bounds__(NTHR, 1) void lstm_mma_kernel(
    const float* __restrict__ b_ih0, const float* __restrict__ b_hh0,
    const float* __restrict__ b_ih1, const float* __restrict__ b_hh1,
    const float* __restrict__ Wd,    const float* __restrict__ bd,
    float* __restrict__ out)
{
    extern __shared__ char dsmem[];
    const unsigned sb = smem_u32(dsmem);
    const int tid  = threadIdx.x;
    const int cta  = blockIdx.x;
    const int tile = cta & 31;
    const int s    = cta >> 5;

    // layer0: 36 units (x: 0-3, h0: 4-35), split boundaries
    const int cs0[5] = {0, 9, 18, 27, 36};

    for (int t = 0; t < TQ; ++t) {
        // Layer 0
        gemm_phase(g_xh + (size_t)t * INQ, g_xl + (size_t)t * INQ, TQ * INQ,
                   g_h0h, g_h0l, HQ, 4,
                   g_W0h, g_W0l, KV0,
                   cs0[s], cs0[s + 1], sb, tile, s);
        grid_bar();
        cell_phase(g_c0, g_h0h, g_h0l, nullptr, b_ih0, b_hh0);
        grid_bar();

        // Layer 1
        gemm_phase(g_h0h, g_h0l, HQ,
                   g_h1h, g_h1l, HQ, 32,
                   g_W1h, g_W1l, KV1,
                   16 * s, 16 * s + 16, sb, tile, s);
        grid_bar();
        cell_phase(g_c1, g_h1h, g_h1l, g_h1f, b_ih1, b_hh1);
        grid_bar();
    }

    // Dense head: CTA b computes out[b][0..1] from fp32 h1
    {
        float* red = (float*)dsmem;
        const int b = cta;
        float s0 = 0.f, s1 = 0.f;
        for (int n = tid; n < HQ; n += NTHR) {
            float hv = g_h1f[(size_t)b * HQ + n];
            s0 += hv * Wd[n];
            s1 += hv * Wd[HQ + n];
        }
        red[tid] = s0; red[NTHR + tid] = s1;
        __syncthreads();
        for (int off = NTHR / 2; off > 0; off >>= 1) {
            if (tid < off) {
                red[tid] += red[tid + off];
                red[NTHR + tid] += red[NTHR + tid + off];
            }
            __syncthreads();
        }
        if (tid == 0) {
            out[b * 2 + 0] = tanhf(red[0] + bd[0]);
            out[b * 2 + 1] = tanhf(red[NTHR] + bd[1]);
        }
    }
}

// ---------------------------------------------------------------------------
// Launch: 4 graph nodes total (tiny graph; no upload-leak)
// ---------------------------------------------------------------------------
extern "C" void kernel_launch(void* const* d_in, const int* in_sizes, int n_in,
                              void* d_out, int out_size)
{
    const float* x     = (const float*)d_in[0];
    const float* W_ih0 = (const float*)d_in[1];
    const float* W_hh0 = (const float*)d_in[2];
    const float* b_ih0 = (const float*)d_in[3];
    const float* b_hh0 = (const float*)d_in[4];
    const float* W_ih1 = (const float*)d_in[5];
    const float* W_hh1 = (const float*)d_in[6];
    const float* b_ih1 = (const float*)d_in[7];
    const float* b_hh1 = (const float*)d_in[8];
    const float* Wd    = (const float*)d_in[9];
    const float* bd    = (const float*)d_in[10];
    float* out = (float*)d_out;

    const int smem_bytes = NBUF * (int)STAGEB;   // 122880
    cudaFuncSetAttribute(lstm_mma_kernel,
                         cudaFuncAttributeMaxDynamicSharedMemorySize, smem_bytes);

    init_state_kernel<<<(BQ * HQ + 255) / 256, 256>>>();
    init_x_kernel<<<(BQ * TQ * INQ + 255) / 256, 256>>>(x);
    init_w_kernel<<<2048, 256>>>(W_ih0, W_hh0, W_ih1, W_hh1);

    lstm_mma_kernel<<<NCTA, NTHR, smem_bytes>>>(
        b_ih0, b_hh0, b_ih1, b_hh1, Wd, bd, out);
}

// round 6
// speedup vs baseline: 2.5232x; 1.2742x over previous
#include <cuda_runtime.h>
#include <cuda_bf16.h>
#include <math.h>

// Problem constants
#define BQ   128
#define TQ   256
#define INQ  128
#define HQ   1024
#define NCTA 128      // 32 col-tiles x 4 K-splits; all co-resident
#define NTHR 256

#define NU0  36       // layer0 units of k32: 4 (x) + 32 (h0)
#define NU1  64       // layer1 units: 32 (h0) + 32 (h1)
#define TILE16K 16384u
#define NBUF 4        // bulk pipeline depth (4 x 32KB stage)

// ---------------------------------------------------------------------------
// Device globals. Operand tiles are stored CONTIGUOUS + PRE-SWIZZLED so one
// cp.async.bulk per (A,W) suffices per k32 unit.
// Tile block (16KB) = [hi 8KB | lo 8KB]; within 8KB: row r (128), 32 bf16,
// byte off = r*64 + ((seg ^ ((r>>1)&3))<<4) + (k&7)*2   (seg = k>>3)
// ---------------------------------------------------------------------------
__device__ __align__(1024) unsigned char g_W0t[32u * NU0 * TILE16K]; // 18.9MB
__device__ __align__(1024) unsigned char g_W1t[32u * NU1 * TILE16K]; // 33.6MB
__device__ __align__(1024) unsigned char g_xt[(unsigned)TQ * 4u * TILE16K]; // 16MB
__device__ __align__(1024) unsigned char g_h0t[32u * TILE16K];       // 512KB
__device__ __align__(1024) unsigned char g_h1t[32u * TILE16K];
__device__ float g_h1f[BQ * HQ];
__device__ float g_c0[BQ * HQ];
__device__ float g_c1[BQ * HQ];
// Partial gate sums: [s][tile][b][c]
__device__ float g_part[4u * 32u * 128u * 128u];

__device__ unsigned g_bar_count = 0;
__device__ unsigned g_bar_gen   = 0;

__device__ __forceinline__ unsigned off_in_tile(int r, int k) {
    return (unsigned)(r * 64 + ((((k >> 3) ^ ((r >> 1) & 3))) << 4) + ((k & 7) << 1));
}

// ---------------------------------------------------------------------------
// PTX helpers (sm_90 baseline — no 'a'-gated features)
// ---------------------------------------------------------------------------
__device__ __forceinline__ unsigned smem_u32(const void* p) {
    unsigned a;
    asm("{ .reg .u64 t; cvta.to.shared.u64 t, %1; cvt.u32.u64 %0, t; }"
        : "=r"(a) : "l"(p));
    return a;
}
__device__ __forceinline__ void mbar_init(unsigned mbar, unsigned cnt) {
    asm volatile("mbarrier.init.shared.b64 [%0], %1;" :: "r"(mbar), "r"(cnt) : "memory");
}
__device__ __forceinline__ void mbar_wait(unsigned mbar, unsigned parity) {
    asm volatile(
        "{\n\t.reg .pred P;\n\t"
        "W_%=:\n\t"
        "mbarrier.try_wait.parity.acquire.cta.shared::cta.b64 P, [%0], %1, 0x989680;\n\t"
        "@!P bra W_%=;\n\t}"
        :: "r"(mbar), "r"(parity) : "memory");
}
__device__ __forceinline__ void mbar_expect_tx(unsigned mbar, unsigned bytes) {
    asm volatile("mbarrier.arrive.expect_tx.shared.b64 _, [%0], %1;"
                 :: "r"(mbar), "r"(bytes) : "memory");
}
__device__ __forceinline__ void bulk_g2s(unsigned dst, const void* src,
                                         unsigned bytes, unsigned mbar) {
    asm volatile(
        "cp.async.bulk.shared::cluster.global.mbarrier::complete_tx::bytes "
        "[%0], [%1], %2, [%3];"
        :: "r"(dst), "l"(src), "r"(bytes), "r"(mbar) : "memory");
}
__device__ __forceinline__ void fence_async() {
    asm volatile("fence.proxy.async.shared::cta;" ::: "memory");
}
__device__ __forceinline__ void ldsm4(unsigned& r0, unsigned& r1,
                                      unsigned& r2, unsigned& r3, unsigned a) {
    asm volatile("ldmatrix.sync.aligned.m8n8.x4.shared.b16 {%0,%1,%2,%3}, [%4];"
                 : "=r"(r0), "=r"(r1), "=r"(r2), "=r"(r3) : "r"(a));
}
__device__ __forceinline__ void ldsm2(unsigned& r0, unsigned& r1, unsigned a) {
    asm volatile("ldmatrix.sync.aligned.m8n8.x2.shared.b16 {%0,%1}, [%2];"
                 : "=r"(r0), "=r"(r1) : "r"(a));
}
__device__ __forceinline__ void mma16816(float* d, const unsigned* a, const unsigned* b) {
    asm volatile(
        "mma.sync.aligned.m16n8k16.row.col.f32.bf16.bf16.f32 "
        "{%0,%1,%2,%3}, {%4,%5,%6,%7}, {%8,%9}, {%0,%1,%2,%3};"
        : "+f"(d[0]), "+f"(d[1]), "+f"(d[2]), "+f"(d[3])
        : "r"(a[0]), "r"(a[1]), "r"(a[2]), "r"(a[3]), "r"(b[0]), "r"(b[1]));
}

// ---------------------------------------------------------------------------
// Grid barrier (all NCTA CTAs co-resident)
// ---------------------------------------------------------------------------
__device__ __forceinline__ void grid_bar() {
    __syncthreads();
    if (threadIdx.x == 0) {
        __threadfence();
        unsigned my = *(volatile unsigned*)&g_bar_gen;
        if (atomicAdd(&g_bar_count, 1u) == NCTA - 1u) {
            *(volatile unsigned*)&g_bar_count = 0;
            __threadfence();
            atomicExch(&g_bar_gen, my + 1u);
        } else {
            while (*(volatile unsigned*)&g_bar_gen == my) { }
        }
        __threadfence();
    }
    __syncthreads();
}

// ---------------------------------------------------------------------------
// Init kernels (per replay; deterministic)
// ---------------------------------------------------------------------------
__device__ __forceinline__ void split_store(float v, unsigned char* hi_ptr) {
    __nv_bfloat16 h = __float2bfloat16(v);
    __nv_bfloat16 l = __float2bfloat16(v - __bfloat162float(h));
    *(__nv_bfloat16*)hi_ptr = h;
    *(__nv_bfloat16*)(hi_ptr + 8192) = l;
}

__global__ void init_state_kernel() {
    int i = blockIdx.x * blockDim.x + threadIdx.x;
    // zero h tiles (hi+lo) and c state
    if (i < (32 * 16384) / 4) {
        ((unsigned*)g_h0t)[i] = 0u;
        ((unsigned*)g_h1t)[i] = 0u;
    }
    if (i < BQ * HQ) { g_c0[i] = 0.f; g_c1[i] = 0.f; }
}
__global__ void init_x_kernel(const float* __restrict__ x) {
    int i = blockIdx.x * blockDim.x + threadIdx.x;   // = b*32768 + t*128 + k
    if (i >= BQ * TQ * INQ) return;
    int k = i & 127, t = (i >> 7) & 255, b = i >> 15;
    int u = k >> 5, kl = k & 31;
    unsigned char* dst = g_xt + (size_t)(t * 4 + u) * TILE16K + off_in_tile(b, kl);
    split_store(x[i], dst);
}
__global__ void init_w_kernel(
    const float* __restrict__ W_ih0, const float* __restrict__ W_hh0,
    const float* __restrict__ W_ih1, const float* __restrict__ W_hh1)
{
    const unsigned N0 = 32u * NU0 * 4096u;   // elements (per hi tile) in W0
    const unsigned N1 = 32u * NU1 * 4096u;
    for (unsigned i = blockIdx.x * blockDim.x + threadIdx.x; i < N0 + N1;
         i += gridDim.x * blockDim.x) {
        if (i < N0) {
            unsigned kl = i & 31u, r = (i >> 5) & 127u;
            unsigned rest = i >> 12, u = rest % NU0, tile = rest / NU0;
            unsigned gcol = ((r >> 5) << 10) + tile * 32u + (r & 31u);
            unsigned k = u * 32u + kl;
            float v = (k < 128u) ? W_ih0[(size_t)gcol * 128u + k]
                                 : W_hh0[(size_t)gcol * 1024u + (k - 128u)];
            split_store(v, g_W0t + (size_t)(tile * NU0 + u) * TILE16K + off_in_tile(r, kl));
        } else {
            unsigned j = i - N0;
            unsigned kl = j & 31u, r = (j >> 5) & 127u;
            unsigned rest = j >> 12, u = rest & 63u, tile = rest >> 6;
            unsigned gcol = ((r >> 5) << 10) + tile * 32u + (r & 31u);
            unsigned k = u * 32u + kl;
            float v = (k < 1024u) ? W_ih1[(size_t)gcol * 1024u + k]
                                  : W_hh1[(size_t)gcol * 1024u + (k - 1024u)];
            split_store(v, g_W1t + (size_t)(tile * NU1 + u) * TILE16K + off_in_tile(r, kl));
        }
    }
}

// ---------------------------------------------------------------------------
// GEMM phase: per k32 unit, 2 bulk copies (A 16KB, W 16KB), mbarrier pipeline,
// 3-term split bf16 HMMA. Warp grid 2(M) x 4(N), warp tile 64x32.
// ---------------------------------------------------------------------------
__device__ void gemm_phase(
    const unsigned char* __restrict__ pxa, int uxsplit,
    const unsigned char* __restrict__ pha,
    const unsigned char* __restrict__ pw,
    int ulo, int uhi,
    unsigned sb, int tile, int s, unsigned* ph)
{
    const int tid  = threadIdx.x;
    const int lane = tid & 31;
    const int wid  = tid >> 5;
    const int wm   = wid >> 2;
    const int wn   = wid & 3;
    const int nU   = uhi - ulo;

    float acc[4][4][4];
    #pragma unroll
    for (int m = 0; m < 4; ++m)
        #pragma unroll
        for (int n = 0; n < 4; ++n)
            #pragma unroll
            for (int r = 0; r < 4; ++r) acc[m][n][r] = 0.f;

    auto issue = [&](int idx) {
        int u = ulo + idx;
        const unsigned char* asrc = (u < uxsplit)
            ? pxa + (size_t)u * TILE16K
            : pha + (size_t)(u - uxsplit) * TILE16K;
        const unsigned char* wsrc = pw + (size_t)u * TILE16K;
        int buf = idx & (NBUF - 1);
        unsigned mbar = sb + (unsigned)buf * 8u;
        unsigned dst  = sb + 1024u + (unsigned)buf * 32768u;
        mbar_expect_tx(mbar, 32768u);
        bulk_g2s(dst,           asrc, TILE16K, mbar);
        bulk_g2s(dst + TILE16K, wsrc, TILE16K, mbar);
    };

    if (tid == 0) {
        int np = nU < NBUF ? nU : NBUF;
        for (int p = 0; p < np; ++p) issue(p);
    }

    for (int i = 0; i < nU; ++i) {
        int buf = i & (NBUF - 1);
        mbar_wait(sb + (unsigned)buf * 8u, ph[buf]);
        ph[buf] ^= 1u;
        unsigned bA = sb + 1024u + (unsigned)buf * 32768u;   // A hi (lo +8192)
        unsigned bW = bA + TILE16K;                          // W hi (lo +8192)

        #pragma unroll
        for (int j = 0; j < 2; ++j) {
            int rA = wm * 64 + (lane & 15);
            unsigned aH = bA + (unsigned)(rA * 64)
                        + ((unsigned)((j * 2 + (lane >> 4)) ^ ((rA >> 1) & 3)) << 4);
            unsigned AH[4][4], AL[4][4];
            #pragma unroll
            for (int m = 0; m < 4; ++m) {
                ldsm4(AH[m][0], AH[m][1], AH[m][2], AH[m][3], aH + m * 1024u);
                ldsm4(AL[m][0], AL[m][1], AL[m][2], AL[m][3], aH + m * 1024u + 8192u);
            }
            int rW = wn * 32 + (lane & 7);
            unsigned wH = bW + (unsigned)(rW * 64)
                        + ((unsigned)((j * 2 + ((lane >> 3) & 1)) ^ ((rW >> 1) & 3)) << 4);
            unsigned WH[4][2], WL[4][2];
            #pragma unroll
            for (int n = 0; n < 4; ++n) {
                ldsm2(WH[n][0], WH[n][1], wH + n * 512u);
                ldsm2(WL[n][0], WL[n][1], wH + n * 512u + 8192u);
            }
            #pragma unroll
            for (int m = 0; m < 4; ++m)
                #pragma unroll
                for (int n = 0; n < 4; ++n) {
                    mma16816(acc[m][n], AH[m], WH[n]);
                    mma16816(acc[m][n], AL[m], WH[n]);
                    mma16816(acc[m][n], AH[m], WL[n]);
                }
        }
        __syncthreads();
        if (tid == 0 && i + NBUF < nU) issue(i + NBUF);
    }

    // Epilogue: D fragments -> g_part[s][tile][b][c]
    float* pb = g_part + ((size_t)(s * 32 + tile) << 14);
    #pragma unroll
    for (int m = 0; m < 4; ++m)
        #pragma unroll
        for (int n = 0; n < 4; ++n) {
            int b = wm * 64 + m * 16 + (lane >> 2);
            int c = wn * 32 + n * 8 + (lane & 3) * 2;
            *(float2*)(pb + (size_t)b * 128 + c) =
                make_float2(acc[m][n][0], acc[m][n][1]);
            *(float2*)(pb + (size_t)(b + 8) * 128 + c) =
                make_float2(acc[m][n][2], acc[m][n][3]);
        }
}

// ---------------------------------------------------------------------------
// Cell phase: sum 4 partials + biases; update c; write h into swizzled tiles.
// ---------------------------------------------------------------------------
__device__ __forceinline__ void cell_phase(
    float* __restrict__ cst, unsigned char* __restrict__ htile,
    float* __restrict__ hf,
    const float* __restrict__ b_ih, const float* __restrict__ b_hh)
{
    const int gtid = blockIdx.x * NTHR + threadIdx.x;
    #pragma unroll
    for (int it = 0; it < (BQ * HQ) / (NCTA * NTHR); ++it) {
        int gid  = gtid + it * NCTA * NTHR;   // = b*1024 + n
        int n    = gid & 1023;
        int b    = gid >> 10;
        int tile = n >> 5, nl = n & 31;

        float g4[4];
        #pragma unroll
        for (int g = 0; g < 4; ++g) {
            float sum = b_ih[g * 1024 + n] + b_hh[g * 1024 + n];
            #pragma unroll
            for (int s2 = 0; s2 < 4; ++s2)
                sum += g_part[((size_t)(s2 * 32 + tile) << 14)
                              + (size_t)b * 128 + g * 32 + nl];
            g4[g] = sum;
        }
        float si = 1.f / (1.f + expf(-g4[0]));
        float sf = 1.f / (1.f + expf(-g4[1]));
        float so = 1.f / (1.f + expf(-g4[3]));
        float cn = sf * cst[gid] + si * tanhf(g4[2]);
        cst[gid] = cn;
        float hv = so * tanhf(cn);
        split_store(hv, htile + (size_t)tile * TILE16K + off_in_tile(b, nl));
        if (hf) hf[gid] = hv;
    }
}

// ---------------------------------------------------------------------------
// Main persistent kernel
// ---------------------------------------------------------------------------
__global__ __launch_bounds__(NTHR, 1) void lstm_mma_kernel(
    const float* __restrict__ b_ih0, const float* __restrict__ b_hh0,
    const float* __restrict__ b_ih1, const float* __restrict__ b_hh1,
    const float* __restrict__ Wd,    const float* __restrict__ bd,
    float* __restrict__ out)
{
    extern __shared__ __align__(1024) unsigned char dsmem[];
    const unsigned sb = smem_u32(dsmem);
    const int tid  = threadIdx.x;
    const int cta  = blockIdx.x;
    const int tile = cta & 31;
    const int s    = cta >> 5;

    if (tid == 0) {
        #pragma unroll
        for (int i = 0; i < NBUF; ++i) mbar_init(sb + i * 8u, 1u);
        fence_async();
    }
    __syncthreads();

    unsigned ph[NBUF] = {0, 0, 0, 0};

    const unsigned char* w0 = g_W0t + (size_t)tile * NU0 * TILE16K;
    const unsigned char* w1 = g_W1t + (size_t)tile * NU1 * TILE16K;

    for (int t = 0; t < TQ; ++t) {
        // Layer 0: units 0..35 (0-3 = x(t), 4-35 = h0)
        gemm_phase(g_xt + (size_t)t * 4 * TILE16K, 4, g_h0t, w0,
                   s * 9, s * 9 + 9, sb, tile, s, ph);
        grid_bar();
        cell_phase(g_c0, g_h0t, nullptr, b_ih0, b_hh0);
        grid_bar();

        // Layer 1: units 0..63 (0-31 = h0, 32-63 = h1)
        gemm_phase(g_h0t, 32, g_h1t, w1,
                   s * 16, s * 16 + 16, sb, tile, s, ph);
        grid_bar();
        cell_phase(g_c1, g_h1t, g_h1f, b_ih1, b_hh1);
        grid_bar();
    }

    // Dense head: CTA b computes out[b][0..1]
    {
        float* red = (float*)dsmem;
        const int b = cta;
        float s0 = 0.f, s1 = 0.f;
        for (int n = tid; n < HQ; n += NTHR) {
            float hv = g_h1f[(size_t)b * HQ + n];
            s0 += hv * Wd[n];
            s1 += hv * Wd[HQ + n];
        }
        __syncthreads();
        red[tid] = s0; red[NTHR + tid] = s1;
        __syncthreads();
        for (int off = NTHR / 2; off > 0; off >>= 1) {
            if (tid < off) {
                red[tid] += red[tid + off];
                red[NTHR + tid] += red[NTHR + tid + off];
            }
            __syncthreads();
        }
        if (tid == 0) {
            out[b * 2 + 0] = tanhf(red[0] + bd[0]);
            out[b * 2 + 1] = tanhf(red[NTHR] + bd[1]);
        }
    }
}

// ---------------------------------------------------------------------------
// Launch: 4 graph nodes
// ---------------------------------------------------------------------------
extern "C" void kernel_launch(void* const* d_in, const int* in_sizes, int n_in,
                              void* d_out, int out_size)
{
    const float* x     = (const float*)d_in[0];
    const float* W_ih0 = (const float*)d_in[1];
    const float* W_hh0 = (const float*)d_in[2];
    const float* b_ih0 = (const float*)d_in[3];
    const float* b_hh0 = (const float*)d_in[4];
    const float* W_ih1 = (const float*)d_in[5];
    const float* W_hh1 = (const float*)d_in[6];
    const float* b_ih1 = (const float*)d_in[7];
    const float* b_hh1 = (const float*)d_in[8];
    const float* Wd    = (const float*)d_in[9];
    const float* bd    = (const float*)d_in[10];
    float* out = (float*)d_out;

    const int smem_bytes = 1024 + NBUF * 32768;   // 132096
    cudaFuncSetAttribute(lstm_mma_kernel,
                         cudaFuncAttributeMaxDynamicSharedMemorySize, smem_bytes);

    init_state_kernel<<<(32 * 16384 / 4 + 255) / 256, 256>>>();
    init_x_kernel<<<(BQ * TQ * INQ + 255) / 256, 256>>>(x);
    init_w_kernel<<<2048, 256>>>(W_ih0, W_hh0, W_ih1, W_hh1);

    lstm_mma_kernel<<<NCTA, NTHR, smem_bytes>>>(
        b_ih0, b_hh0, b_ih1, b_hh1, Wd, bd, out);
}

// round 7
// speedup vs baseline: 2.5554x; 1.0127x over previous
#include <cuda_runtime.h>
#include <cuda_bf16.h>
#include <math.h>

// Problem constants
#define BQ   128
#define TQ   256
#define INQ  128
#define HQ   1024
#define NCTA 128      // 32 col-tiles x 4 K-splits; all co-resident
#define NTHR 256

#define NU0  36       // layer0 units of k32: 4 (x) + 32 (h0)
#define TILE16K 16384u
#define NBUF 4        // bulk pipeline depth (4 x 32KB stage)

// ---------------------------------------------------------------------------
// Device globals. Operand tiles contiguous + pre-swizzled: one cp.async.bulk
// per (A,W) per k32 unit. Tile (16KB) = [hi 8KB | lo 8KB]; within 8KB:
// byte off = r*64 + ((seg ^ ((r>>1)&3))<<4) + (k&7)*2,  seg = k>>3.
// ---------------------------------------------------------------------------
__device__ __align__(1024) unsigned char g_W0t[32u * NU0 * TILE16K];
__device__ __align__(1024) unsigned char g_W1t[32u * 64u * TILE16K];
__device__ __align__(1024) unsigned char g_xt[(unsigned)TQ * 4u * TILE16K];
__device__ __align__(1024) unsigned char g_h0t[32u * TILE16K];
__device__ __align__(1024) unsigned char g_h1t[32u * TILE16K];
__device__ float g_h1f[BQ * HQ];
__device__ float g_c0[BQ * HQ];
__device__ float g_c1[BQ * HQ];
// Partial gate sums: layer0 4 slots, layer1 8 slots (two phase-halves)
__device__ float g_part0[4u * 32u * 128u * 128u];
__device__ float g_part1[8u * 32u * 128u * 128u];

__device__ unsigned g_bar_count = 0;
__device__ unsigned g_bar_gen   = 0;

__device__ __forceinline__ unsigned off_in_tile(int r, int k) {
    return (unsigned)(r * 64 + ((((k >> 3) ^ ((r >> 1) & 3))) << 4) + ((k & 7) << 1));
}

// ---------------------------------------------------------------------------
// PTX helpers (sm_90 baseline — no 'a'-gated features)
// ---------------------------------------------------------------------------
__device__ __forceinline__ unsigned smem_u32(const void* p) {
    unsigned a;
    asm("{ .reg .u64 t; cvta.to.shared.u64 t, %1; cvt.u32.u64 %0, t; }"
        : "=r"(a) : "l"(p));
    return a;
}
__device__ __forceinline__ void mbar_init(unsigned mbar, unsigned cnt) {
    asm volatile("mbarrier.init.shared.b64 [%0], %1;" :: "r"(mbar), "r"(cnt) : "memory");
}
__device__ __forceinline__ void mbar_wait(unsigned mbar, unsigned parity) {
    asm volatile(
        "{\n\t.reg .pred P;\n\t"
        "W_%=:\n\t"
        "mbarrier.try_wait.parity.acquire.cta.shared::cta.b64 P, [%0], %1, 0x989680;\n\t"
        "@!P bra W_%=;\n\t}"
        :: "r"(mbar), "r"(parity) : "memory");
}
__device__ __forceinline__ void mbar_expect_tx(unsigned mbar, unsigned bytes) {
    asm volatile("mbarrier.arrive.expect_tx.shared.b64 _, [%0], %1;"
                 :: "r"(mbar), "r"(bytes) : "memory");
}
__device__ __forceinline__ void bulk_g2s(unsigned dst, const void* src,
                                         unsigned bytes, unsigned mbar) {
    asm volatile(
        "cp.async.bulk.shared::cluster.global.mbarrier::complete_tx::bytes "
        "[%0], [%1], %2, [%3];"
        :: "r"(dst), "l"(src), "r"(bytes), "r"(mbar) : "memory");
}
__device__ __forceinline__ void fence_async() {
    asm volatile("fence.proxy.async.shared::cta;" ::: "memory");
}
__device__ __forceinline__ void ldsm4(unsigned& r0, unsigned& r1,
                                      unsigned& r2, unsigned& r3, unsigned a) {
    asm volatile("ldmatrix.sync.aligned.m8n8.x4.shared.b16 {%0,%1,%2,%3}, [%4];"
                 : "=r"(r0), "=r"(r1), "=r"(r2), "=r"(r3) : "r"(a));
}
__device__ __forceinline__ void ldsm2(unsigned& r0, unsigned& r1, unsigned a) {
    asm volatile("ldmatrix.sync.aligned.m8n8.x2.shared.b16 {%0,%1}, [%2];"
                 : "=r"(r0), "=r"(r1) : "r"(a));
}
__device__ __forceinline__ void mma16816(float* d, const unsigned* a, const unsigned* b) {
    asm volatile(
        "mma.sync.aligned.m16n8k16.row.col.f32.bf16.bf16.f32 "
        "{%0,%1,%2,%3}, {%4,%5,%6,%7}, {%8,%9}, {%0,%1,%2,%3};"
        : "+f"(d[0]), "+f"(d[1]), "+f"(d[2]), "+f"(d[3])
        : "r"(a[0]), "r"(a[1]), "r"(a[2]), "r"(a[3]), "r"(b[0]), "r"(b[1]));
}

// ---------------------------------------------------------------------------
// Grid barrier (all NCTA CTAs co-resident)
// ---------------------------------------------------------------------------
__device__ __forceinline__ void grid_bar() {
    __syncthreads();
    if (threadIdx.x == 0) {
        __threadfence();
        unsigned my = *(volatile unsigned*)&g_bar_gen;
        if (atomicAdd(&g_bar_count, 1u) == NCTA - 1u) {
            *(volatile unsigned*)&g_bar_count = 0;
            __threadfence();
            atomicExch(&g_bar_gen, my + 1u);
        } else {
            while (*(volatile unsigned*)&g_bar_gen == my) { }
        }
        __threadfence();
    }
    __syncthreads();
}

// ---------------------------------------------------------------------------
// Init kernels (per replay; deterministic)
// ---------------------------------------------------------------------------
__device__ __forceinline__ void split_store(float v, unsigned char* hi_ptr) {
    __nv_bfloat16 h = __float2bfloat16(v);
    __nv_bfloat16 l = __float2bfloat16(v - __bfloat162float(h));
    *(__nv_bfloat16*)hi_ptr = h;
    *(__nv_bfloat16*)(hi_ptr + 8192) = l;
}

__global__ void init_state_kernel() {
    int i = blockIdx.x * blockDim.x + threadIdx.x;
    if (i < (32 * 16384) / 4) {
        ((unsigned*)g_h0t)[i] = 0u;
        ((unsigned*)g_h1t)[i] = 0u;
    }
    if (i < BQ * HQ) { g_c0[i] = 0.f; g_c1[i] = 0.f; }
}
__global__ void init_x_kernel(const float* __restrict__ x) {
    int i = blockIdx.x * blockDim.x + threadIdx.x;   // = b*32768 + t*128 + k
    if (i >= BQ * TQ * INQ) return;
    int k = i & 127, t = (i >> 7) & 255, b = i >> 15;
    int u = k >> 5, kl = k & 31;
    unsigned char* dst = g_xt + (size_t)(t * 4 + u) * TILE16K + off_in_tile(b, kl);
    split_store(x[i], dst);
}
__global__ void init_w_kernel(
    const float* __restrict__ W_ih0, const float* __restrict__ W_hh0,
    const float* __restrict__ W_ih1, const float* __restrict__ W_hh1)
{
    const unsigned N0 = 32u * NU0 * 4096u;
    const unsigned N1 = 32u * 64u * 4096u;
    for (unsigned i = blockIdx.x * blockDim.x + threadIdx.x; i < N0 + N1;
         i += gridDim.x * blockDim.x) {
        if (i < N0) {
            unsigned kl = i & 31u, r = (i >> 5) & 127u;
            unsigned rest = i >> 12, u = rest % NU0, tile = rest / NU0;
            unsigned gcol = ((r >> 5) << 10) + tile * 32u + (r & 31u);
            unsigned k = u * 32u + kl;
            float v = (k < 128u) ? W_ih0[(size_t)gcol * 128u + k]
                                 : W_hh0[(size_t)gcol * 1024u + (k - 128u)];
            split_store(v, g_W0t + (size_t)(tile * NU0 + u) * TILE16K + off_in_tile(r, kl));
        } else {
            unsigned j = i - N0;
            unsigned kl = j & 31u, r = (j >> 5) & 127u;
            unsigned rest = j >> 12, u = rest & 63u, tile = rest >> 6;
            unsigned gcol = ((r >> 5) << 10) + tile * 32u + (r & 31u);
            unsigned k = u * 32u + kl;
            float v = (k < 1024u) ? W_ih1[(size_t)gcol * 1024u + k]
                                  : W_hh1[(size_t)gcol * 1024u + (k - 1024u)];
            split_store(v, g_W1t + (size_t)(tile * 64u + u) * TILE16K + off_in_tile(r, kl));
        }
    }
}

// ---------------------------------------------------------------------------
// Cell phase: sum NS partial slots + biases; update c; write swizzled h tiles.
// ---------------------------------------------------------------------------
template <int NS>
__device__ __forceinline__ void cell_phase(
    float* __restrict__ cst, unsigned char* __restrict__ htile,
    float* __restrict__ hf, const float* __restrict__ part,
    const float* __restrict__ b_ih, const float* __restrict__ b_hh)
{
    const int gtid = blockIdx.x * NTHR + threadIdx.x;
    #pragma unroll
    for (int it = 0; it < (BQ * HQ) / (NCTA * NTHR); ++it) {
        int gid  = gtid + it * NCTA * NTHR;   // = b*1024 + n
        int n    = gid & 1023;
        int b    = gid >> 10;
        int tile = n >> 5, nl = n & 31;

        float g4[4];
        #pragma unroll
        for (int g = 0; g < 4; ++g) {
            float sum = b_ih[g * 1024 + n] + b_hh[g * 1024 + n];
            #pragma unroll
            for (int s2 = 0; s2 < NS; ++s2)
                sum += part[((size_t)(s2 * 32 + tile) << 14)
                            + (size_t)b * 128 + g * 32 + nl];
            g4[g] = sum;
        }
        float si = 1.f / (1.f + expf(-g4[0]));
        float sf = 1.f / (1.f + expf(-g4[1]));
        float so = 1.f / (1.f + expf(-g4[3]));
        float cn = sf * cst[gid] + si * tanhf(g4[2]);
        cst[gid] = cn;
        float hv = so * tanhf(cn);
        split_store(hv, htile + (size_t)tile * TILE16K + off_in_tile(b, nl));
        if (hf) hf[gid] = hv;
    }
}

// ---------------------------------------------------------------------------
// GEMM phase with optional embedded cell (CELLK: 0 none, 1 cell0, 2 cell1).
// Prologue bulks are issued FIRST, then the cell runs (hiding load latency),
// then the MMA loop consumes the pipeline.
// ---------------------------------------------------------------------------
template <int CELLK>
__device__ void gemm_phase(
    const unsigned char* __restrict__ pxa, int uxsplit,
    const unsigned char* __restrict__ pha,
    const unsigned char* __restrict__ pw,
    int ulo, int nU, float* __restrict__ pslot,
    unsigned sb, unsigned* ph,
    const float* b_ih0, const float* b_hh0,
    const float* b_ih1, const float* b_hh1)
{
    const int tid  = threadIdx.x;
    const int lane = tid & 31;
    const int wid  = tid >> 5;
    const int wm   = wid >> 2;
    const int wn   = wid & 3;

    float acc[4][4][4];
    #pragma unroll
    for (int m = 0; m < 4; ++m)
        #pragma unroll
        for (int n = 0; n < 4; ++n)
            #pragma unroll
            for (int r = 0; r < 4; ++r) acc[m][n][r] = 0.f;

    auto issue = [&](int idx) {
        int u = ulo + idx;
        const unsigned char* asrc = (u < uxsplit)
            ? pxa + (size_t)u * TILE16K
            : pha + (size_t)(u - uxsplit) * TILE16K;
        const unsigned char* wsrc = pw + (size_t)u * TILE16K;
        int buf = idx & (NBUF - 1);
        unsigned mbar = sb + (unsigned)buf * 8u;
        unsigned dst  = sb + 1024u + (unsigned)buf * 32768u;
        mbar_expect_tx(mbar, 32768u);
        bulk_g2s(dst,           asrc, TILE16K, mbar);
        bulk_g2s(dst + TILE16K, wsrc, TILE16K, mbar);
    };

    if (tid == 0) {
        int np = nU < NBUF ? nU : NBUF;
        for (int p = 0; p < np; ++p) issue(p);
    }

    // Embedded cell: overlaps the bulk-load latency + fills the tensor ramp.
    if (CELLK == 1)
        cell_phase<4>(g_c0, g_h0t, nullptr, g_part0, b_ih0, b_hh0);
    else if (CELLK == 2)
        cell_phase<8>(g_c1, g_h1t, g_h1f, g_part1, b_ih1, b_hh1);

    for (int i = 0; i < nU; ++i) {
        int buf = i & (NBUF - 1);
        mbar_wait(sb + (unsigned)buf * 8u, ph[buf]);
        ph[buf] ^= 1u;
        unsigned bA = sb + 1024u + (unsigned)buf * 32768u;   // A hi (lo +8192)
        unsigned bW = bA + TILE16K;                          // W hi (lo +8192)

        #pragma unroll
        for (int j = 0; j < 2; ++j) {
            int rA = wm * 64 + (lane & 15);
            unsigned aH = bA + (unsigned)(rA * 64)
                        + ((unsigned)((j * 2 + (lane >> 4)) ^ ((rA >> 1) & 3)) << 4);
            unsigned AH[4][4], AL[4][4];
            #pragma unroll
            for (int m = 0; m < 4; ++m) {
                ldsm4(AH[m][0], AH[m][1], AH[m][2], AH[m][3], aH + m * 1024u);
                ldsm4(AL[m][0], AL[m][1], AL[m][2], AL[m][3], aH + m * 1024u + 8192u);
            }
            int rW = wn * 32 + (lane & 7);
            unsigned wH = bW + (unsigned)(rW * 64)
                        + ((unsigned)((j * 2 + ((lane >> 3) & 1)) ^ ((rW >> 1) & 3)) << 4);
            unsigned WH[4][2], WL[4][2];
            #pragma unroll
            for (int n = 0; n < 4; ++n) {
                ldsm2(WH[n][0], WH[n][1], wH + n * 512u);
                ldsm2(WL[n][0], WL[n][1], wH + n * 512u + 8192u);
            }
            #pragma unroll
            for (int m = 0; m < 4; ++m)
                #pragma unroll
                for (int n = 0; n < 4; ++n) {
                    mma16816(acc[m][n], AH[m], WH[n]);
                    mma16816(acc[m][n], AL[m], WH[n]);
                    mma16816(acc[m][n], AH[m], WL[n]);
                }
        }
        __syncthreads();
        if (tid == 0 && i + NBUF < nU) issue(i + NBUF);
    }

    // Epilogue: D fragments -> pslot[b][c]
    #pragma unroll
    for (int m = 0; m < 4; ++m)
        #pragma unroll
        for (int n = 0; n < 4; ++n) {
            int b = wm * 64 + m * 16 + (lane >> 2);
            int c = wn * 32 + n * 8 + (lane & 3) * 2;
            *(float2*)(pslot + (size_t)b * 128 + c) =
                make_float2(acc[m][n][0], acc[m][n][1]);
            *(float2*)(pslot + (size_t)(b + 8) * 128 + c) =
                make_float2(acc[m][n][2], acc[m][n][3]);
        }
}

// ---------------------------------------------------------------------------
// Main persistent kernel: 3 phases per step, cells embedded in gemm phases.
// ---------------------------------------------------------------------------
__global__ __launch_bounds__(NTHR, 1) void lstm_mma_kernel(
    const float* __restrict__ b_ih0, const float* __restrict__ b_hh0,
    const float* __restrict__ b_ih1, const float* __restrict__ b_hh1,
    const float* __restrict__ Wd,    const float* __restrict__ bd,
    float* __restrict__ out)
{
    extern __shared__ __align__(1024) unsigned char dsmem[];
    const unsigned sb = smem_u32(dsmem);
    const int tid  = threadIdx.x;
    const int cta  = blockIdx.x;
    const int tile = cta & 31;
    const int s    = cta >> 5;

    if (tid == 0) {
        #pragma unroll
        for (int i = 0; i < NBUF; ++i) mbar_init(sb + i * 8u, 1u);
        fence_async();
    }
    __syncthreads();

    unsigned ph[NBUF] = {0, 0, 0, 0};

    const unsigned char* w0 = g_W0t + (size_t)tile * NU0 * TILE16K;
    const unsigned char* w1 = g_W1t + (size_t)tile * 64u * TILE16K;
    float* p0slot  = g_part0 + ((size_t)(s * 32 + tile) << 14);
    float* p1aslot = g_part1 + ((size_t)(s * 32 + tile) << 14);
    float* p1bslot = g_part1 + ((size_t)((4 + s) * 32 + tile) << 14);

    for (int t = 0; t < TQ; ++t) {
        // P1: gemm0(t) [9 units: x(0-3), h0(4-35)] + embedded cell1(t-1)
        if (t > 0)
            gemm_phase<2>(g_xt + (size_t)t * 4 * TILE16K, 4, g_h0t, w0,
                          s * 9, 9, p0slot, sb, ph,
                          b_ih0, b_hh0, b_ih1, b_hh1);
        else
            gemm_phase<0>(g_xt + (size_t)t * 4 * TILE16K, 4, g_h0t, w0,
                          s * 9, 9, p0slot, sb, ph,
                          b_ih0, b_hh0, b_ih1, b_hh1);
        grid_bar();

        // P2: gemm1 h1-half [units 32+s*8 .. +8, A = h1 tiles] + cell0(t)
        gemm_phase<1>(nullptr, 32, g_h1t + (size_t)(-32) * 0, w1,
                      32 + s * 8, 8, p1aslot, sb, ph,
                      b_ih0, b_hh0, b_ih1, b_hh1);
        grid_bar();

        // P3: gemm1 h0-half [units s*8 .. +8, A = h0 tiles], no cell
        gemm_phase<0>(nullptr, 0, g_h0t, w1,
                      s * 8, 8, p1bslot, sb, ph,
                      b_ih0, b_hh0, b_ih1, b_hh1);
        grid_bar();
    }

    // Final cell1(255)
    cell_phase<8>(g_c1, g_h1t, g_h1f, g_part1, b_ih1, b_hh1);
    grid_bar();

    // Dense head: CTA b computes out[b][0..1]
    {
        float* red = (float*)dsmem;
        const int b = cta;
        float s0 = 0.f, s1 = 0.f;
        for (int n = tid; n < HQ; n += NTHR) {
            float hv = g_h1f[(size_t)b * HQ + n];
            s0 += hv * Wd[n];
            s1 += hv * Wd[HQ + n];
        }
        __syncthreads();
        red[tid] = s0; red[NTHR + tid] = s1;
        __syncthreads();
        for (int off = NTHR / 2; off > 0; off >>= 1) {
            if (tid < off) {
                red[tid] += red[tid + off];
                red[NTHR + tid] += red[NTHR + tid + off];
            }
            __syncthreads();
        }
        if (tid == 0) {
            out[b * 2 + 0] = tanhf(red[0] + bd[0]);
            out[b * 2 + 1] = tanhf(red[NTHR] + bd[1]);
        }
    }
}

// ---------------------------------------------------------------------------
// Launch: 4 graph nodes
// ---------------------------------------------------------------------------
extern "C" void kernel_launch(void* const* d_in, const int* in_sizes, int n_in,
                              void* d_out, int out_size)
{
    const float* x     = (const float*)d_in[0];
    const float* W_ih0 = (const float*)d_in[1];
    const float* W_hh0 = (const float*)d_in[2];
    const float* b_ih0 = (const float*)d_in[3];
    const float* b_hh0 = (const float*)d_in[4];
    const float* W_ih1 = (const float*)d_in[5];
    const float* W_hh1 = (const float*)d_in[6];
    const float* b_ih1 = (const float*)d_in[7];
    const float* b_hh1 = (const float*)d_in[8];
    const float* Wd    = (const float*)d_in[9];
    const float* bd    = (const float*)d_in[10];
    float* out = (float*)d_out;

    const int smem_bytes = 1024 + NBUF * 32768;   // 132096
    cudaFuncSetAttribute(lstm_mma_kernel,
                         cudaFuncAttributeMaxDynamicSharedMemorySize, smem_bytes);

    init_state_kernel<<<(32 * 16384 / 4 + 255) / 256, 256>>>();
    init_x_kernel<<<(BQ * TQ * INQ + 255) / 256, 256>>>(x);
    init_w_kernel<<<2048, 256>>>(W_ih0, W_hh0, W_ih1, W_hh1);

    lstm_mma_kernel<<<NCTA, NTHR, smem_bytes>>>(
        b_ih0, b_hh0, b_ih1, b_hh1, Wd, bd, out);
}